// round 2
// baseline (speedup 1.0000x reference)
#include <cuda_runtime.h>
#include <stdint.h>

#define T_SEQ 2560
#define HID   7168
#define QLRD  1536
#define NH    64
#define HD    128
#define NQ    8192
#define TQ    512
#define TB    2048
#define KSPLIT 8
#define KCHUNK (HID / KSPLIT)   // 896
#define NEGBIG (-1000000000.0f)

// ------------------- device scratch (no allocs allowed) -------------------
__device__ __align__(16) float g_kpart[KSPLIT * T_SEQ * HD]; // split-K partials
__device__ __align__(16) float g_k[T_SEQ * HD];              // LN+rope k (unused by score, kept for debug)
__device__ __align__(16) float g_kT[HD * T_SEQ];             // k transposed [d][s]
__device__ __align__(16) float g_q[TQ * NQ];                 // q rows 2048..2559 (roped)
__device__ __align__(16) float g_w[TQ * NH];                 // scaled weights
__device__ __align__(16) float g_score[TQ * T_SEQ];          // index scores (s <= t valid)

// ------------------- generic fp32 SGEMM 128x128, BK=8, 256 thr, 8x8 micro -------------------
// which==0 -> C = g_kpart (+ blockIdx.z * zstride), which==1 -> C = g_q
__global__ __launch_bounds__(256) void sgemm128(
    const float* __restrict__ A, int lda,
    const float* __restrict__ B, int ldb,
    int which, int ldc, int kchunk, size_t zstride)
{
    __shared__ float As[8][132];
    __shared__ float Bs[8][132];

    const int tid = threadIdx.x;
    const int tx = tid & 15, ty = tid >> 4;
    const float* Ab = A + (size_t)blockIdx.x * 128 * lda;
    const float* Bb = B + (size_t)blockIdx.y * 128;
    float* Cb = (which == 0 ? g_kpart : g_q)
              + (size_t)blockIdx.z * zstride
              + (size_t)blockIdx.x * 128 * ldc + (size_t)blockIdx.y * 128;

    const int arow = tid >> 1, aoff = (tid & 1) * 4;
    const int bkk = tid >> 5, bcol = (tid & 31) * 4;

    float acc[8][8];
#pragma unroll
    for (int i = 0; i < 8; i++)
#pragma unroll
        for (int j = 0; j < 8; j++) acc[i][j] = 0.0f;

    int k0 = blockIdx.z * kchunk;
    const int kend = k0 + kchunk;
    for (; k0 < kend; k0 += 8) {
        float4 av = *(const float4*)(Ab + (size_t)arow * lda + k0 + aoff);
        float4 bv = *(const float4*)(Bb + (size_t)(k0 + bkk) * ldb + bcol);
        As[aoff + 0][arow] = av.x; As[aoff + 1][arow] = av.y;
        As[aoff + 2][arow] = av.z; As[aoff + 3][arow] = av.w;
        *(float4*)&Bs[bkk][bcol] = bv;
        __syncthreads();
#pragma unroll
        for (int kk = 0; kk < 8; kk++) {
            float4 a0 = *(const float4*)&As[kk][ty * 8];
            float4 a1 = *(const float4*)&As[kk][ty * 8 + 4];
            float4 b0 = *(const float4*)&Bs[kk][tx * 8];
            float4 b1 = *(const float4*)&Bs[kk][tx * 8 + 4];
            float a[8] = {a0.x, a0.y, a0.z, a0.w, a1.x, a1.y, a1.z, a1.w};
            float b[8] = {b0.x, b0.y, b0.z, b0.w, b1.x, b1.y, b1.z, b1.w};
#pragma unroll
            for (int i = 0; i < 8; i++)
#pragma unroll
                for (int j = 0; j < 8; j++)
                    acc[i][j] = fmaf(a[i], b[j], acc[i][j]);
        }
        __syncthreads();
    }
#pragma unroll
    for (int i = 0; i < 8; i++) {
        float* cr = Cb + (size_t)(ty * 8 + i) * ldc + tx * 8;
        float4 v0 = make_float4(acc[i][0], acc[i][1], acc[i][2], acc[i][3]);
        float4 v1 = make_float4(acc[i][4], acc[i][5], acc[i][6], acc[i][7]);
        *(float4*)cr = v0;
        *(float4*)(cr + 4) = v1;
    }
}

// ------------------- split-K reduce + LayerNorm + RoPE for k -------------------
__global__ __launch_bounds__(128) void k_postproc(
    const float* __restrict__ gamma, const float* __restrict__ beta,
    const float* __restrict__ fcos, const float* __restrict__ fsin)
{
    const int t = blockIdx.x;
    const int d = threadIdx.x;   // 128 threads
    float v = 0.0f;
#pragma unroll
    for (int p = 0; p < KSPLIT; p++)
        v += g_kpart[(size_t)p * T_SEQ * HD + (size_t)t * HD + d];

    __shared__ float red[128];
    __shared__ float buf[128];
    red[d] = v; __syncthreads();
#pragma unroll
    for (int s = 64; s > 0; s >>= 1) { if (d < s) red[d] += red[d + s]; __syncthreads(); }
    const float mu = red[0] * (1.0f / 128.0f);
    __syncthreads();
    const float diff = v - mu;
    red[d] = diff * diff; __syncthreads();
#pragma unroll
    for (int s = 64; s > 0; s >>= 1) { if (d < s) red[d] += red[d + s]; __syncthreads(); }
    const float var = red[0] * (1.0f / 128.0f);
    const float inv = __frsqrt_rn(var + 1e-6f);
    const float nrm = diff * inv * gamma[d] + beta[d];
    buf[d] = nrm; __syncthreads();

    float outv;
    if (d < 32) {
        float c = fcos[t * 32 + d], s = fsin[t * 32 + d];
        outv = buf[d] * c - buf[d + 32] * s;
    } else if (d < 64) {
        float c = fcos[t * 32 + d - 32], s = fsin[t * 32 + d - 32];
        outv = buf[d - 32] * s + buf[d] * c;
    } else {
        outv = nrm;
    }
    g_k[(size_t)t * HD + d] = outv;
    g_kT[(size_t)d * T_SEQ + t] = outv;
}

// ------------------- RoPE on q (rows 2048..2559, first 64 dims of each head) -------------------
__global__ void q_rope(const float* __restrict__ fcos, const float* __restrict__ fsin)
{
    int idx = blockIdx.x * blockDim.x + threadIdx.x;  // over TQ*NH*32
    if (idx >= TQ * NH * 32) return;
    int i = idx & 31;
    int h = (idx >> 5) & 63;
    int tq = idx >> 11;
    int t = TB + tq;
    float c = fcos[t * 32 + i], s = fsin[t * 32 + i];
    float* q = g_q + (size_t)tq * NQ + h * HD;
    float x1 = q[i], x2 = q[i + 32];
    q[i]      = x1 * c - x2 * s;
    q[i + 32] = x1 * s + x2 * c;
}

// ------------------- weights for the 512 active rows: w[t] = x[t] @ wproj * scale -------------------
__global__ __launch_bounds__(256) void w_gemv(const float* __restrict__ x, const float* __restrict__ wproj)
{
    const int tq = blockIdx.x;
    const int tid = threadIdx.x;
    const int h = tid & 63;
    const int kg = tid >> 6;  // 0..3
    const float* xr = x + (size_t)(TB + tq) * HID + (size_t)kg * (HID / 4);
    const float* wp = wproj + (size_t)kg * (HID / 4) * NH + h;
    float acc = 0.0f;
    for (int k = 0; k < HID / 4; k += 4) {
        float4 xv = *(const float4*)(xr + k);
        acc = fmaf(xv.x, wp[(k + 0) * NH], acc);
        acc = fmaf(xv.y, wp[(k + 1) * NH], acc);
        acc = fmaf(xv.z, wp[(k + 2) * NH], acc);
        acc = fmaf(xv.w, wp[(k + 3) * NH], acc);
    }
    __shared__ float red[4][64];
    red[kg][h] = acc; __syncthreads();
    if (tid < 64) {
        float s = red[0][tid] + red[1][tid] + red[2][tid] + red[3][tid];
        s = (s * 0.125f) * 0.08838834764831843f;  // * 64^-0.5 * 128^-0.5, two fp32 mults like ref
        g_w[tq * NH + tid] = s;
    }
}

// ------------------- score: per (2 t-rows x 64 heads, 128 s) tile GEMM + fused relu*w head reduce ---
__global__ __launch_bounds__(256) void score_gemm()
{
    __shared__ float As[8][132];
    __shared__ float Bs[8][132];
    __shared__ float red[16][128];

    const int bs = blockIdx.x;   // s tile 0..19
    const int bt = blockIdx.y;   // t-pair 0..255
    const int tid = threadIdx.x;
    const int tx = tid & 15, ty = tid >> 4;
    const float* A  = g_q + (size_t)bt * 128 * HD;   // 128 rows of (tq,h)
    const float* Bt = g_kT + (size_t)bs * 128;

    const int arow = tid >> 1, aoff = (tid & 1) * 4;
    const int bkk = tid >> 5, bcol = (tid & 31) * 4;

    float acc[8][8];
#pragma unroll
    for (int i = 0; i < 8; i++)
#pragma unroll
        for (int j = 0; j < 8; j++) acc[i][j] = 0.0f;

#pragma unroll
    for (int k0 = 0; k0 < HD; k0 += 8) {
        float4 av = *(const float4*)(A + (size_t)arow * HD + k0 + aoff);
        float4 bv = *(const float4*)(Bt + (size_t)(k0 + bkk) * T_SEQ + bcol);
        As[aoff + 0][arow] = av.x; As[aoff + 1][arow] = av.y;
        As[aoff + 2][arow] = av.z; As[aoff + 3][arow] = av.w;
        *(float4*)&Bs[bkk][bcol] = bv;
        __syncthreads();
#pragma unroll
        for (int kk = 0; kk < 8; kk++) {
            float4 a0 = *(const float4*)&As[kk][ty * 8];
            float4 a1 = *(const float4*)&As[kk][ty * 8 + 4];
            float4 b0 = *(const float4*)&Bs[kk][tx * 8];
            float4 b1 = *(const float4*)&Bs[kk][tx * 8 + 4];
            float a[8] = {a0.x, a0.y, a0.z, a0.w, a1.x, a1.y, a1.z, a1.w};
            float b[8] = {b0.x, b0.y, b0.z, b0.w, b1.x, b1.y, b1.z, b1.w};
#pragma unroll
            for (int i = 0; i < 8; i++)
#pragma unroll
                for (int j = 0; j < 8; j++)
                    acc[i][j] = fmaf(a[i], b[j], acc[i][j]);
        }
        __syncthreads();
    }

    // epilogue: relu, * w[t,h], reduce over the 64 head-rows of each t
    const int tt = ty >> 3;             // which t of the pair
    const int hbase = (ty & 7) * 8;     // head base for this thread's 8 rows
    const int tq = bt * 2 + tt;
    float wv[8];
#pragma unroll
    for (int i = 0; i < 8; i++) wv[i] = g_w[tq * NH + hbase + i];

    float part[8];
#pragma unroll
    for (int j = 0; j < 8; j++) {
        float s = 0.0f;
#pragma unroll
        for (int i = 0; i < 8; i++)
            s = fmaf(fmaxf(acc[i][j], 0.0f), wv[i], s);
        part[j] = s;
    }
    {
        float4 p0 = make_float4(part[0], part[1], part[2], part[3]);
        float4 p1 = make_float4(part[4], part[5], part[6], part[7]);
        *(float4*)&red[ty][tx * 8] = p0;
        *(float4*)&red[ty][tx * 8 + 4] = p1;
    }
    __syncthreads();
    const int col = tid & 127, tt2 = tid >> 7;
    float s = 0.0f;
#pragma unroll
    for (int g = 0; g < 8; g++) s += red[tt2 * 8 + g][col];
    g_score[(size_t)(bt * 2 + tt2) * T_SEQ + bs * 128 + col] = s;
}

// ------------------- fixed fill for rows t < 2048 (selection is data-independent) -------------------
__global__ void fill_fixed(float* __restrict__ out)
{
    size_t i = (size_t)blockIdx.x * blockDim.x + threadIdx.x;
    const size_t total = (size_t)TB * T_SEQ / 4;
    if (i >= total) return;
    size_t s4 = (i % (T_SEQ / 4)) * 4;
    float v = (s4 < TB) ? 0.0f : NEGBIG;
    float4 f = make_float4(v, v, v, v);
    ((float4*)out)[i] = f;
}

// ------------------- exact top-2048 for rows t >= 2048 via radix select -------------------
__global__ __launch_bounds__(256) void topk_select(float* __restrict__ out)
{
    __shared__ unsigned keys[T_SEQ];
    __shared__ unsigned char flags[T_SEQ];
    __shared__ int redc[9];
    __shared__ int rlt[8], req[8];
    __shared__ int cnts[256];

    const int tq = blockIdx.x;
    const int t = TB + tq;
    const int n = t + 1;                 // candidates: s in [0, t]
    const int tid = threadIdx.x;
    const int lane = tid & 31, wid = tid >> 5;
    const float* srow = g_score + (size_t)tq * T_SEQ;

    for (int i = tid; i < n; i += 256) {
        unsigned b = __float_as_uint(srow[i]);
        keys[i] = b ^ ((b & 0x80000000u) ? 0xFFFFFFFFu : 0x80000000u);
    }
    __syncthreads();

    const int m0 = tq + 1;               // number of smallest entries to drop
    int m = m0;
    unsigned prefix = 0;
    for (int bit = 31; bit >= 0; bit--) {
        const unsigned pshift = prefix >> bit;
        int c = 0;
        for (int i = tid; i < n; i += 256)
            c += ((keys[i] >> bit) == pshift);
#pragma unroll
        for (int o = 16; o; o >>= 1) c += __shfl_xor_sync(0xffffffffu, c, o);
        if (lane == 0) redc[wid] = c;
        __syncthreads();
        if (tid == 0) {
            int tot = 0;
            for (int w = 0; w < 8; w++) tot += redc[w];
            redc[8] = tot;
        }
        __syncthreads();
        const int cnt = redc[8];
        if (m > cnt) { m -= cnt; prefix |= (1u << bit); }
        __syncthreads();
    }
    const unsigned theta = prefix;       // value of the m0-th smallest key

    // counts below / equal
    int clt = 0, ceq = 0;
    for (int i = tid; i < n; i += 256) {
        unsigned k = keys[i];
        clt += (k < theta);
        ceq += (k == theta);
    }
#pragma unroll
    for (int o = 16; o; o >>= 1) {
        clt += __shfl_xor_sync(0xffffffffu, clt, o);
        ceq += __shfl_xor_sync(0xffffffffu, ceq, o);
    }
    if (lane == 0) { rlt[wid] = clt; req[wid] = ceq; }
    __syncthreads();
    int count_lt = 0, count_eq = 0;
    for (int w = 0; w < 8; w++) { count_lt += rlt[w]; count_eq += req[w]; }
    const int keep_eq = count_eq - (m0 - count_lt);  // keep lowest-index ties (lax.top_k)

    // rank ties by index: blocked count + serial exclusive scan + local walk
    const int chunk = (n + 255) / 256;
    const int beg = tid * chunk;
    const int end = (beg + chunk < n) ? (beg + chunk) : n;
    int local = 0;
    for (int i = beg; i < end; i++) local += (keys[i] == theta);
    cnts[tid] = local;
    __syncthreads();
    if (tid == 0) {
        int run = 0;
        for (int i = 0; i < 256; i++) { int c = cnts[i]; cnts[i] = run; run += c; }
    }
    __syncthreads();
    int rank = cnts[tid];
    for (int i = beg; i < end; i++)
        if (keys[i] == theta) { flags[i] = (rank < keep_eq) ? 1 : 0; rank++; }
    __syncthreads();

    float* orow = out + (size_t)t * T_SEQ;
    for (int s = tid; s < T_SEQ; s += 256) {
        float v = NEGBIG;
        if (s < n) {
            unsigned k = keys[s];
            if (k > theta || (k == theta && flags[s])) v = 0.0f;
        }
        orow[s] = v;
    }
}

// ------------------- launch -------------------
extern "C" void kernel_launch(void* const* d_in, const int* in_sizes, int n_in,
                              void* d_out, int out_size)
{
    (void)in_sizes; (void)n_in; (void)out_size;
    const float* x     = (const float*)d_in[0];
    const float* qr    = (const float*)d_in[1];
    const float* fcos  = (const float*)d_in[2];
    const float* fsin  = (const float*)d_in[3];
    // d_in[4] = mask (structure exploited, not read)
    const float* wq_b  = (const float*)d_in[5];
    const float* wk_w  = (const float*)d_in[6];
    const float* kgam  = (const float*)d_in[7];
    const float* kbet  = (const float*)d_in[8];
    const float* wproj = (const float*)d_in[9];
    float* out = (float*)d_out;

    // k = x @ wk_w  (split-K partials)
    sgemm128<<<dim3(20, 1, KSPLIT), 256>>>(x, HID, wk_w, HD, 0, HD, KCHUNK, (size_t)T_SEQ * HD);
    // reduce + LN + rope -> g_k, g_kT
    k_postproc<<<T_SEQ, 128>>>(kgam, kbet, fcos, fsin);
    // weights for active rows
    w_gemv<<<TQ, 256>>>(x, wproj);
    // q = qr[2048:] @ wq_b
    sgemm128<<<dim3(TQ / 128, NQ / 128, 1), 256>>>(qr + (size_t)TB * QLRD, QLRD, wq_b, NQ, 1, NQ, QLRD, 0);
    q_rope<<<(TQ * NH * 32 + 255) / 256, 256>>>(fcos, fsin);
    // scores for 512 rows
    score_gemm<<<dim3(T_SEQ / 128, TQ / 2), 256>>>();
    // output
    fill_fixed<<<((TB * T_SEQ / 4) + 255) / 256, 256>>>(out);
    topk_select<<<TQ, 256>>>(out);
}

// round 3
// speedup vs baseline: 1.0004x; 1.0004x over previous
#include <cuda_runtime.h>
#include <stdint.h>

#define T_SEQ 2560
#define HID   7168
#define QLRD  1536
#define NH    64
#define HD    128
#define NQ    8192
#define TQ    512
#define TB    2048
#define KSPLIT 8
#define KCHUNK (HID / KSPLIT)   // 896
#define NEGBIG (-1000000000.0f)

typedef unsigned long long ull;

// ------------------- device scratch -------------------
__device__ __align__(16) float g_kpart[KSPLIT * T_SEQ * HD];
__device__ __align__(16) float g_k[T_SEQ * HD];
__device__ __align__(16) float g_kT[HD * T_SEQ];
__device__ __align__(16) float g_q[TQ * NQ];
__device__ __align__(16) float g_w[TQ * NH];
__device__ __align__(16) float g_score[TQ * T_SEQ];

// ------------------- packed fp32x2 helpers -------------------
#define FFMA2(c, a, b) asm("fma.rn.f32x2 %0, %1, %2, %3;" : "=l"(c) : "l"(a), "l"(b), "l"(c))

__device__ __forceinline__ uint32_t su(const void* p) {
    return (uint32_t)__cvta_generic_to_shared(p);
}
__device__ __forceinline__ void lds2u64(ull& a, ull& b, uint32_t addr) {
    asm volatile("ld.shared.v2.b64 {%0,%1},[%2];" : "=l"(a), "=l"(b) : "r"(addr));
}
__device__ __forceinline__ float2 upk(ull v) {
    float2 r;
    asm("mov.b64 {%0,%1},%2;" : "=f"(r.x), "=f"(r.y) : "l"(v));
    return r;
}

// A-dup buffer: [8 kk][16 groups * 20 floats]  (each row value duplicated: (a,a))
#define A_STRIDE 320
#define B_STRIDE 132

// store one float4 of A (rows-major) into duplicated smem layout
#define STORE_A(dst, v) do { \
    float _vv[4] = {(v).x, (v).y, (v).z, (v).w}; \
    _Pragma("unroll") \
    for (int _c = 0; _c < 4; _c++) { \
        int _o = (aoff + _c) * A_STRIDE + (arow >> 3) * 20 + (arow & 7) * 2; \
        (dst)[_o] = _vv[_c]; (dst)[_o + 1] = _vv[_c]; \
    } } while (0)

#define INNER_FFMA2() do { \
    ull a2[8], bp[4]; \
    lds2u64(a2[0], a2[1], aa); \
    lds2u64(a2[2], a2[3], aa + 16); \
    lds2u64(a2[4], a2[5], aa + 32); \
    lds2u64(a2[6], a2[7], aa + 48); \
    lds2u64(bp[0], bp[1], ba); \
    lds2u64(bp[2], bp[3], ba + 16); \
    _Pragma("unroll") \
    for (int _i = 0; _i < 8; _i++) { \
        FFMA2(acc2[_i][0], a2[_i], bp[0]); \
        FFMA2(acc2[_i][1], a2[_i], bp[1]); \
        FFMA2(acc2[_i][2], a2[_i], bp[2]); \
        FFMA2(acc2[_i][3], a2[_i], bp[3]); \
    } \
    aa += A_STRIDE * 4; ba += B_STRIDE * 4; } while (0)

// ------------------- fp32x2 SGEMM 128x128, BK=8, 256 thr, 8x8 micro, double-buffered ----
// which==0 -> C = g_kpart + blockIdx.z*zstride, which==1 -> C = g_q
__global__ __launch_bounds__(256, 2) void sgemm128_v2(
    const float* __restrict__ A, int lda,
    const float* __restrict__ B, int ldb,
    int which, int ldc, int kchunk, size_t zstride)
{
    __shared__ float AsD[2][8 * A_STRIDE];
    __shared__ float Bs[2][8 * B_STRIDE];

    const int tid = threadIdx.x;
    const int tx = tid & 15, ty = tid >> 4;
    const float* Ab = A + (size_t)blockIdx.x * 128 * lda;
    const float* Bb = B + (size_t)blockIdx.y * 128;
    float* Cb = (which == 0 ? g_kpart : g_q)
              + (size_t)blockIdx.z * zstride
              + (size_t)blockIdx.x * 128 * ldc + (size_t)blockIdx.y * 128;

    const int arow = tid >> 1, aoff = (tid & 1) * 4;
    const int bkk = tid >> 5, bcol = (tid & 31) * 4;
    const float* Ap = Ab + (size_t)arow * lda + aoff;
    const float* Bp = Bb + (size_t)bkk * ldb + bcol;

    ull acc2[8][4];
#pragma unroll
    for (int i = 0; i < 8; i++)
#pragma unroll
        for (int j = 0; j < 4; j++) acc2[i][j] = 0ull;

    const uint32_t a_base = su(&AsD[0][0]) + (ty * 20) * 4;
    const uint32_t b_base = su(&Bs[0][0]) + (tx * 8) * 4;
    const uint32_t ABUF = 8 * A_STRIDE * 4, BBUF = 8 * B_STRIDE * 4;

    const int k0 = blockIdx.z * kchunk;
    const int niter = kchunk / 8;

    float4 av = *(const float4*)(Ap + k0);
    float4 bv = *(const float4*)(Bp + (size_t)k0 * ldb);
    STORE_A(AsD[0], av);
    *(float4*)&Bs[0][bkk * B_STRIDE + bcol] = bv;
    __syncthreads();

    int buf = 0;
    for (int it = 0; it < niter; it++) {
        const bool more = (it + 1 < niter);
        if (more) {
            av = *(const float4*)(Ap + k0 + (it + 1) * 8);
            bv = *(const float4*)(Bp + (size_t)(k0 + (it + 1) * 8) * ldb);
        }
        uint32_t aa = a_base + buf * ABUF;
        uint32_t ba = b_base + buf * BBUF;
#pragma unroll
        for (int kk = 0; kk < 8; kk++) INNER_FFMA2();
        if (more) {
            int nb = buf ^ 1;
            STORE_A(AsD[nb], av);
            *(float4*)&Bs[nb][bkk * B_STRIDE + bcol] = bv;
        }
        __syncthreads();
        buf ^= 1;
    }

#pragma unroll
    for (int i = 0; i < 8; i++) {
        float* cr = Cb + (size_t)(ty * 8 + i) * ldc + tx * 8;
        float2 p0 = upk(acc2[i][0]), p1 = upk(acc2[i][1]);
        float2 p2 = upk(acc2[i][2]), p3 = upk(acc2[i][3]);
        *(float4*)cr       = make_float4(p0.x, p0.y, p1.x, p1.y);
        *(float4*)(cr + 4) = make_float4(p2.x, p2.y, p3.x, p3.y);
    }
}

// ------------------- split-K reduce + LayerNorm + RoPE for k -------------------
__global__ __launch_bounds__(128) void k_postproc(
    const float* __restrict__ gamma, const float* __restrict__ beta,
    const float* __restrict__ fcos, const float* __restrict__ fsin)
{
    const int t = blockIdx.x;
    const int d = threadIdx.x;
    float v = 0.0f;
#pragma unroll
    for (int p = 0; p < KSPLIT; p++)
        v += g_kpart[(size_t)p * T_SEQ * HD + (size_t)t * HD + d];

    __shared__ float red[128];
    __shared__ float buf[128];
    red[d] = v; __syncthreads();
#pragma unroll
    for (int s = 64; s > 0; s >>= 1) { if (d < s) red[d] += red[d + s]; __syncthreads(); }
    const float mu = red[0] * (1.0f / 128.0f);
    __syncthreads();
    const float diff = v - mu;
    red[d] = diff * diff; __syncthreads();
#pragma unroll
    for (int s = 64; s > 0; s >>= 1) { if (d < s) red[d] += red[d + s]; __syncthreads(); }
    const float var = red[0] * (1.0f / 128.0f);
    const float inv = __frsqrt_rn(var + 1e-6f);
    const float nrm = diff * inv * gamma[d] + beta[d];
    buf[d] = nrm; __syncthreads();

    float outv;
    if (d < 32) {
        float c = fcos[t * 32 + d], s = fsin[t * 32 + d];
        outv = buf[d] * c - buf[d + 32] * s;
    } else if (d < 64) {
        float c = fcos[t * 32 + d - 32], s = fsin[t * 32 + d - 32];
        outv = buf[d - 32] * s + buf[d] * c;
    } else {
        outv = nrm;
    }
    g_k[(size_t)t * HD + d] = outv;
    g_kT[(size_t)d * T_SEQ + t] = outv;
}

// ------------------- RoPE on q -------------------
__global__ void q_rope(const float* __restrict__ fcos, const float* __restrict__ fsin)
{
    int idx = blockIdx.x * blockDim.x + threadIdx.x;
    if (idx >= TQ * NH * 32) return;
    int i = idx & 31;
    int h = (idx >> 5) & 63;
    int tq = idx >> 11;
    int t = TB + tq;
    float c = fcos[t * 32 + i], s = fsin[t * 32 + i];
    float* q = g_q + (size_t)tq * NQ + h * HD;
    float x1 = q[i], x2 = q[i + 32];
    q[i]      = x1 * c - x2 * s;
    q[i + 32] = x1 * s + x2 * c;
}

// ------------------- weights for active rows -------------------
__global__ __launch_bounds__(256) void w_gemv(const float* __restrict__ x, const float* __restrict__ wproj)
{
    const int tq = blockIdx.x;
    const int tid = threadIdx.x;
    const int h = tid & 63;
    const int kg = tid >> 6;
    const float* xr = x + (size_t)(TB + tq) * HID + (size_t)kg * (HID / 4);
    const float* wp = wproj + (size_t)kg * (HID / 4) * NH + h;
    float acc = 0.0f;
    for (int k = 0; k < HID / 4; k += 4) {
        float4 xv = *(const float4*)(xr + k);
        acc = fmaf(xv.x, wp[(k + 0) * NH], acc);
        acc = fmaf(xv.y, wp[(k + 1) * NH], acc);
        acc = fmaf(xv.z, wp[(k + 2) * NH], acc);
        acc = fmaf(xv.w, wp[(k + 3) * NH], acc);
    }
    __shared__ float red[4][64];
    red[kg][h] = acc; __syncthreads();
    if (tid < 64) {
        float s = red[0][tid] + red[1][tid] + red[2][tid] + red[3][tid];
        s = (s * 0.125f) * 0.08838834764831843f;
        g_w[tq * NH + tid] = s;
    }
}

// ------------------- score GEMM (fp32x2) + fused relu*w head reduce -------------------
__global__ __launch_bounds__(256, 2) void score_gemm_v2()
{
    __shared__ float AsD[2][8 * A_STRIDE];
    __shared__ float Bs[2][8 * B_STRIDE];
    __shared__ float red[16][128];

    const int bs = blockIdx.x;   // s tile
    const int bt = blockIdx.y;   // t-pair
    const int tid = threadIdx.x;
    const int tx = tid & 15, ty = tid >> 4;
    const float* A  = g_q + (size_t)bt * 128 * HD;
    const float* Bt = g_kT + (size_t)bs * 128;

    const int arow = tid >> 1, aoff = (tid & 1) * 4;
    const int bkk = tid >> 5, bcol = (tid & 31) * 4;
    const float* Ap = A + (size_t)arow * HD + aoff;
    const float* Bp = Bt + (size_t)bkk * T_SEQ + bcol;

    ull acc2[8][4];
#pragma unroll
    for (int i = 0; i < 8; i++)
#pragma unroll
        for (int j = 0; j < 4; j++) acc2[i][j] = 0ull;

    const uint32_t a_base = su(&AsD[0][0]) + (ty * 20) * 4;
    const uint32_t b_base = su(&Bs[0][0]) + (tx * 8) * 4;
    const uint32_t ABUF = 8 * A_STRIDE * 4, BBUF = 8 * B_STRIDE * 4;

    float4 av = *(const float4*)(Ap);
    float4 bv = *(const float4*)(Bp);
    STORE_A(AsD[0], av);
    *(float4*)&Bs[0][bkk * B_STRIDE + bcol] = bv;
    __syncthreads();

    int buf = 0;
#pragma unroll
    for (int it = 0; it < HD / 8; it++) {
        const bool more = (it + 1 < HD / 8);
        if (more) {
            av = *(const float4*)(Ap + (it + 1) * 8);
            bv = *(const float4*)(Bp + (size_t)(it + 1) * 8 * T_SEQ);
        }
        uint32_t aa = a_base + buf * ABUF;
        uint32_t ba = b_base + buf * BBUF;
#pragma unroll
        for (int kk = 0; kk < 8; kk++) INNER_FFMA2();
        if (more) {
            int nb = buf ^ 1;
            STORE_A(AsD[nb], av);
            *(float4*)&Bs[nb][bkk * B_STRIDE + bcol] = bv;
        }
        __syncthreads();
        buf ^= 1;
    }

    // epilogue: relu, * w[t,h], reduce over 64 head-rows per t
    const int tt = ty >> 3;
    const int hbase = (ty & 7) * 8;
    const int tq = bt * 2 + tt;
    float wv[8];
#pragma unroll
    for (int i = 0; i < 8; i++) wv[i] = g_w[tq * NH + hbase + i];

    float part[8];
#pragma unroll
    for (int jp = 0; jp < 4; jp++) {
        float sx = 0.0f, sy = 0.0f;
#pragma unroll
        for (int i = 0; i < 8; i++) {
            float2 v = upk(acc2[i][jp]);
            sx = fmaf(fmaxf(v.x, 0.0f), wv[i], sx);
            sy = fmaf(fmaxf(v.y, 0.0f), wv[i], sy);
        }
        part[jp * 2] = sx; part[jp * 2 + 1] = sy;
    }
    *(float4*)&red[ty][tx * 8]     = make_float4(part[0], part[1], part[2], part[3]);
    *(float4*)&red[ty][tx * 8 + 4] = make_float4(part[4], part[5], part[6], part[7]);
    __syncthreads();
    const int col = tid & 127, tt2 = tid >> 7;
    float s = 0.0f;
#pragma unroll
    for (int g = 0; g < 8; g++) s += red[tt2 * 8 + g][col];
    g_score[(size_t)(bt * 2 + tt2) * T_SEQ + bs * 128 + col] = s;
}

// ------------------- fixed fill for rows t < 2048 -------------------
__global__ void fill_fixed(float* __restrict__ out)
{
    size_t i = (size_t)blockIdx.x * blockDim.x + threadIdx.x;
    const size_t total = (size_t)TB * T_SEQ / 4;
    if (i >= total) return;
    size_t s4 = (i % (T_SEQ / 4)) * 4;
    float v = (s4 < TB) ? 0.0f : NEGBIG;
    ((float4*)out)[i] = make_float4(v, v, v, v);
}

// ------------------- exact top-2048 via radix select -------------------
__global__ __launch_bounds__(256) void topk_select(float* __restrict__ out)
{
    __shared__ unsigned keys[T_SEQ];
    __shared__ unsigned char flags[T_SEQ];
    __shared__ int redc[9];
    __shared__ int rlt[8], req[8];
    __shared__ int cnts[256];

    const int tq = blockIdx.x;
    const int t = TB + tq;
    const int n = t + 1;
    const int tid = threadIdx.x;
    const int lane = tid & 31, wid = tid >> 5;
    const float* srow = g_score + (size_t)tq * T_SEQ;

    for (int i = tid; i < n; i += 256) {
        unsigned b = __float_as_uint(srow[i]);
        keys[i] = b ^ ((b & 0x80000000u) ? 0xFFFFFFFFu : 0x80000000u);
    }
    __syncthreads();

    const int m0 = tq + 1;
    int m = m0;
    unsigned prefix = 0;
    for (int bit = 31; bit >= 0; bit--) {
        const unsigned pshift = prefix >> bit;
        int c = 0;
        for (int i = tid; i < n; i += 256)
            c += ((keys[i] >> bit) == pshift);
#pragma unroll
        for (int o = 16; o; o >>= 1) c += __shfl_xor_sync(0xffffffffu, c, o);
        if (lane == 0) redc[wid] = c;
        __syncthreads();
        if (tid == 0) {
            int tot = 0;
            for (int w = 0; w < 8; w++) tot += redc[w];
            redc[8] = tot;
        }
        __syncthreads();
        const int cnt = redc[8];
        if (m > cnt) { m -= cnt; prefix |= (1u << bit); }
        __syncthreads();
    }
    const unsigned theta = prefix;

    int clt = 0, ceq = 0;
    for (int i = tid; i < n; i += 256) {
        unsigned k = keys[i];
        clt += (k < theta);
        ceq += (k == theta);
    }
#pragma unroll
    for (int o = 16; o; o >>= 1) {
        clt += __shfl_xor_sync(0xffffffffu, clt, o);
        ceq += __shfl_xor_sync(0xffffffffu, ceq, o);
    }
    if (lane == 0) { rlt[wid] = clt; req[wid] = ceq; }
    __syncthreads();
    int count_lt = 0, count_eq = 0;
    for (int w = 0; w < 8; w++) { count_lt += rlt[w]; count_eq += req[w]; }
    const int keep_eq = count_eq - (m0 - count_lt);

    const int chunk = (n + 255) / 256;
    const int beg = tid * chunk;
    const int end = (beg + chunk < n) ? (beg + chunk) : n;
    int local = 0;
    for (int i = beg; i < end; i++) local += (keys[i] == theta);
    cnts[tid] = local;
    __syncthreads();
    if (tid == 0) {
        int run = 0;
        for (int i = 0; i < 256; i++) { int c = cnts[i]; cnts[i] = run; run += c; }
    }
    __syncthreads();
    int rank = cnts[tid];
    for (int i = beg; i < end; i++)
        if (keys[i] == theta) { flags[i] = (rank < keep_eq) ? 1 : 0; rank++; }
    __syncthreads();

    float* orow = out + (size_t)t * T_SEQ;
    for (int s = tid; s < T_SEQ; s += 256) {
        float v = NEGBIG;
        if (s < n) {
            unsigned k = keys[s];
            if (k > theta || (k == theta && flags[s])) v = 0.0f;
        }
        orow[s] = v;
    }
}

// ------------------- launch -------------------
extern "C" void kernel_launch(void* const* d_in, const int* in_sizes, int n_in,
                              void* d_out, int out_size)
{
    (void)in_sizes; (void)n_in; (void)out_size;
    const float* x     = (const float*)d_in[0];
    const float* qr    = (const float*)d_in[1];
    const float* fcos  = (const float*)d_in[2];
    const float* fsin  = (const float*)d_in[3];
    const float* wq_b  = (const float*)d_in[5];
    const float* wk_w  = (const float*)d_in[6];
    const float* kgam  = (const float*)d_in[7];
    const float* kbet  = (const float*)d_in[8];
    const float* wproj = (const float*)d_in[9];
    float* out = (float*)d_out;

    sgemm128_v2<<<dim3(20, 1, KSPLIT), 256>>>(x, HID, wk_w, HD, 0, HD, KCHUNK, (size_t)T_SEQ * HD);
    k_postproc<<<T_SEQ, 128>>>(kgam, kbet, fcos, fsin);
    w_gemv<<<TQ, 256>>>(x, wproj);
    sgemm128_v2<<<dim3(TQ / 128, NQ / 128, 1), 256>>>(qr + (size_t)TB * QLRD, QLRD, wq_b, NQ, 1, NQ, QLRD, 0);
    q_rope<<<(TQ * NH * 32 + 255) / 256, 256>>>(fcos, fsin);
    score_gemm_v2<<<dim3(T_SEQ / 128, TQ / 2), 256>>>();
    fill_fixed<<<((TB * T_SEQ / 4) + 255) / 256, 256>>>(out);
    topk_select<<<TQ, 256>>>(out);
}

// round 6
// speedup vs baseline: 1.0112x; 1.0108x over previous
#include <cuda_runtime.h>
#include <cuda_bf16.h>
#include <stdint.h>

#define T_SEQ 2560
#define HID   7168
#define QLRD  1536
#define NH    64
#define HD    128
#define NQ    8192
#define TQ    512
#define TB    2048
#define KSPLIT 8
#define KCHUNK (HID / KSPLIT)
#define NEGBIG (-1000000000.0f)

// ------------------- device scratch -------------------
__device__ __align__(16) float g_kpart[KSPLIT * T_SEQ * HD];
__device__ __align__(16) float g_q[TQ * NQ];
__device__ __align__(16) float g_w[TQ * NH];
__device__ __align__(16) float g_score[TQ * T_SEQ];
// bf16 3-way splits of q (post-rope) and k (post-LN/rope)
__device__ __align__(16) __nv_bfloat16 g_qs0[TQ * NQ];
__device__ __align__(16) __nv_bfloat16 g_qs1[TQ * NQ];
__device__ __align__(16) __nv_bfloat16 g_qs2[TQ * NQ];
__device__ __align__(16) __nv_bfloat16 g_ks0[T_SEQ * HD];
__device__ __align__(16) __nv_bfloat16 g_ks1[T_SEQ * HD];
__device__ __align__(16) __nv_bfloat16 g_ks2[T_SEQ * HD];

// ------------------- mma.sync helpers (baseline PTX, legal on sm_103) -------------------
__device__ __forceinline__ void ldsm4(uint32_t* r, uint32_t addr) {
    asm volatile("ldmatrix.sync.aligned.m8n8.x4.shared.b16 {%0,%1,%2,%3},[%4];"
        : "=r"(r[0]), "=r"(r[1]), "=r"(r[2]), "=r"(r[3]) : "r"(addr));
}
__device__ __forceinline__ void mma16816(float* d, const uint32_t* a, const uint32_t* b) {
    asm volatile("mma.sync.aligned.m16n8k16.row.col.f32.bf16.bf16.f32 "
        "{%0,%1,%2,%3},{%4,%5,%6,%7},{%8,%9},{%0,%1,%2,%3};"
        : "+f"(d[0]), "+f"(d[1]), "+f"(d[2]), "+f"(d[3])
        : "r"(a[0]), "r"(a[1]), "r"(a[2]), "r"(a[3]), "r"(b[0]), "r"(b[1]));
}

#define LDA 72   // padded smem row stride (bf16 units): conflict-free LDSM

// load a 128x64 bf16 tile (row stride rs) into smem at padded stride LDA
__device__ __forceinline__ void load_tile(__nv_bfloat16* dst, const __nv_bfloat16* src,
                                          size_t rs, int tid) {
#pragma unroll
    for (int i = 0; i < 4; i++) {
        int gid = tid + i * 256;
        int r = gid >> 3, g = gid & 7;
        *(uint4*)(dst + r * LDA + g * 8) = *(const uint4*)(src + (size_t)r * rs + g * 8);
    }
}

// ------------------- score: HMMA bf16 3-split/6-product GEMM + fused relu*w reduce ------
// grid (20 s-tiles, 256 m-tiles), 256 threads. C[m=2t*64h][s], K_eff = 6*128
__constant__ int c_aidx[6] = {0, 0, 1, 1, 0, 2};
__constant__ int c_bidx[6] = {0, 1, 0, 1, 2, 0};

__global__ __launch_bounds__(256, 2) void score_mma()
{
    __shared__ __nv_bfloat16 sA[128 * LDA];
    __shared__ __nv_bfloat16 sB[128 * LDA];
    __shared__ float part[8][64];

    const int bs = blockIdx.x, bt = blockIdx.y;
    const int tid = threadIdx.x, l = tid & 31, wid = tid >> 5;
    const int wm = wid & 3, wn = wid >> 2;

    const __nv_bfloat16* qa[3] = {g_qs0, g_qs1, g_qs2};
    const __nv_bfloat16* kb[3] = {g_ks0, g_ks1, g_ks2};

    float acc[2][8][4] = {};

    const uint32_t sAu = (uint32_t)__cvta_generic_to_shared(sA);
    const uint32_t sBu = (uint32_t)__cvta_generic_to_shared(sB);
    uint32_t aAddr[2], bAddr[4];
#pragma unroll
    for (int mi = 0; mi < 2; mi++)
        aAddr[mi] = sAu + ((wm * 32 + mi * 16 + (l & 15)) * LDA + (l >> 4) * 8) * 2;
#pragma unroll
    for (int nj = 0; nj < 4; nj++)
        bAddr[nj] = sBu + ((wn * 64 + nj * 16 + ((l >> 4) * 8) + (l & 7)) * LDA + ((l >> 3) & 1) * 8) * 2;

#pragma unroll 1
    for (int p = 0; p < 6; p++) {
        const __nv_bfloat16* Aball = qa[c_aidx[p]] + (size_t)bt * 128 * HD;
        const __nv_bfloat16* Bball = kb[c_bidx[p]] + (size_t)bs * 128 * HD;
#pragma unroll 1
        for (int kh = 0; kh < 2; kh++) {
            __syncthreads();
            load_tile(sA, Aball + kh * 64, HD, tid);
            load_tile(sB, Bball + kh * 64, HD, tid);
            __syncthreads();
#pragma unroll
            for (int ks = 0; ks < 4; ks++) {
                uint32_t af[2][4], bf[4][4];
                ldsm4(af[0], aAddr[0] + ks * 32);
                ldsm4(af[1], aAddr[1] + ks * 32);
#pragma unroll
                for (int nj = 0; nj < 4; nj++) ldsm4(bf[nj], bAddr[nj] + ks * 32);
#pragma unroll
                for (int mi = 0; mi < 2; mi++)
#pragma unroll
                    for (int ni = 0; ni < 8; ni++)
                        mma16816(acc[mi][ni], af[mi], &bf[ni >> 1][(ni & 1) * 2]);
            }
        }
    }

    // epilogue: relu * w, reduce over this warp's 32 head-rows, then cross-warp
    const int rbase = wm * 32 + (l >> 2);
    const float w0 = g_w[bt * 128 + rbase];
    const float w1 = g_w[bt * 128 + rbase + 8];
    const float w2 = g_w[bt * 128 + rbase + 16];
    const float w3 = g_w[bt * 128 + rbase + 24];
#pragma unroll
    for (int ni = 0; ni < 8; ni++) {
        float s0 = fmaxf(acc[0][ni][0], 0.0f) * w0 + fmaxf(acc[0][ni][2], 0.0f) * w1
                 + fmaxf(acc[1][ni][0], 0.0f) * w2 + fmaxf(acc[1][ni][2], 0.0f) * w3;
        float s1 = fmaxf(acc[0][ni][1], 0.0f) * w0 + fmaxf(acc[0][ni][3], 0.0f) * w1
                 + fmaxf(acc[1][ni][1], 0.0f) * w2 + fmaxf(acc[1][ni][3], 0.0f) * w3;
#pragma unroll
        for (int o = 4; o < 32; o <<= 1) {
            s0 += __shfl_xor_sync(0xffffffffu, s0, o);
            s1 += __shfl_xor_sync(0xffffffffu, s1, o);
        }
        if (l < 4) {
            part[wid][ni * 8 + 2 * l] = s0;
            part[wid][ni * 8 + 2 * l + 1] = s1;
        }
    }
    __syncthreads();
    {
        const int col = tid & 127, tt = tid >> 7;
        const int wa = (col >> 6) * 4 + tt * 2;
        float s = part[wa][col & 63] + part[wa + 1][col & 63];
        g_score[(size_t)(bt * 2 + tt) * T_SEQ + bs * 128 + col] = s;
    }
}

// ------------------- generic fp32 SGEMM 128x128 (known-exact path for k and q) ----------
__global__ __launch_bounds__(256) void sgemm128(
    const float* __restrict__ A, int lda,
    const float* __restrict__ B, int ldb,
    int which, int ldc, int kchunk, size_t zstride)
{
    __shared__ float As[8][132];
    __shared__ float Bs[8][132];

    const int tid = threadIdx.x;
    const int tx = tid & 15, ty = tid >> 4;
    const float* Ab = A + (size_t)blockIdx.x * 128 * lda;
    const float* Bb = B + (size_t)blockIdx.y * 128;
    float* Cb = (which == 0 ? g_kpart : g_q)
              + (size_t)blockIdx.z * zstride
              + (size_t)blockIdx.x * 128 * ldc + (size_t)blockIdx.y * 128;

    const int arow = tid >> 1, aoff = (tid & 1) * 4;
    const int bkk = tid >> 5, bcol = (tid & 31) * 4;

    float acc[8][8];
#pragma unroll
    for (int i = 0; i < 8; i++)
#pragma unroll
        for (int j = 0; j < 8; j++) acc[i][j] = 0.0f;

    int k0 = blockIdx.z * kchunk;
    const int kend = k0 + kchunk;
    for (; k0 < kend; k0 += 8) {
        float4 av = *(const float4*)(Ab + (size_t)arow * lda + k0 + aoff);
        float4 bv = *(const float4*)(Bb + (size_t)(k0 + bkk) * ldb + bcol);
        As[aoff + 0][arow] = av.x; As[aoff + 1][arow] = av.y;
        As[aoff + 2][arow] = av.z; As[aoff + 3][arow] = av.w;
        *(float4*)&Bs[bkk][bcol] = bv;
        __syncthreads();
#pragma unroll
        for (int kk = 0; kk < 8; kk++) {
            float4 a0 = *(const float4*)&As[kk][ty * 8];
            float4 a1 = *(const float4*)&As[kk][ty * 8 + 4];
            float4 b0 = *(const float4*)&Bs[kk][tx * 8];
            float4 b1 = *(const float4*)&Bs[kk][tx * 8 + 4];
            float a[8] = {a0.x, a0.y, a0.z, a0.w, a1.x, a1.y, a1.z, a1.w};
            float b[8] = {b0.x, b0.y, b0.z, b0.w, b1.x, b1.y, b1.z, b1.w};
#pragma unroll
            for (int i = 0; i < 8; i++)
#pragma unroll
                for (int j = 0; j < 8; j++)
                    acc[i][j] = fmaf(a[i], b[j], acc[i][j]);
        }
        __syncthreads();
    }
#pragma unroll
    for (int i = 0; i < 8; i++) {
        float* cr = Cb + (size_t)(ty * 8 + i) * ldc + tx * 8;
        *(float4*)cr       = make_float4(acc[i][0], acc[i][1], acc[i][2], acc[i][3]);
        *(float4*)(cr + 4) = make_float4(acc[i][4], acc[i][5], acc[i][6], acc[i][7]);
    }
}

// ------------------- split-K reduce + LayerNorm + RoPE + bf16x3 split for k -------------
__global__ __launch_bounds__(128) void k_postproc(
    const float* __restrict__ gamma, const float* __restrict__ beta,
    const float* __restrict__ fcos, const float* __restrict__ fsin)
{
    const int t = blockIdx.x;
    const int d = threadIdx.x;
    float v = 0.0f;
#pragma unroll
    for (int p = 0; p < KSPLIT; p++)
        v += g_kpart[(size_t)p * T_SEQ * HD + (size_t)t * HD + d];

    __shared__ float red[128];
    __shared__ float buf[128];
    red[d] = v; __syncthreads();
#pragma unroll
    for (int s = 64; s > 0; s >>= 1) { if (d < s) red[d] += red[d + s]; __syncthreads(); }
    const float mu = red[0] * (1.0f / 128.0f);
    __syncthreads();
    const float diff = v - mu;
    red[d] = diff * diff; __syncthreads();
#pragma unroll
    for (int s = 64; s > 0; s >>= 1) { if (d < s) red[d] += red[d + s]; __syncthreads(); }
    const float var = red[0] * (1.0f / 128.0f);
    const float inv = __frsqrt_rn(var + 1e-6f);
    const float nrm = diff * inv * gamma[d] + beta[d];
    buf[d] = nrm; __syncthreads();

    float outv;
    if (d < 32) {
        float c = fcos[t * 32 + d], s = fsin[t * 32 + d];
        outv = buf[d] * c - buf[d + 32] * s;
    } else if (d < 64) {
        float c = fcos[t * 32 + d - 32], s = fsin[t * 32 + d - 32];
        outv = buf[d - 32] * s + buf[d] * c;
    } else {
        outv = nrm;
    }
    __nv_bfloat16 b0 = __float2bfloat16(outv);
    float r1 = outv - __bfloat162float(b0);
    __nv_bfloat16 b1 = __float2bfloat16(r1);
    float r2 = r1 - __bfloat162float(b1);
    const size_t o = (size_t)t * HD + d;
    g_ks0[o] = b0; g_ks1[o] = b1; g_ks2[o] = __float2bfloat16(r2);
}

// ------------------- RoPE on q (fp32, in place) -------------------
__global__ void q_rope(const float* __restrict__ fcos, const float* __restrict__ fsin)
{
    int idx = blockIdx.x * blockDim.x + threadIdx.x;
    if (idx >= TQ * NH * 32) return;
    int i = idx & 31;
    int h = (idx >> 5) & 63;
    int tq = idx >> 11;
    int t = TB + tq;
    float c = fcos[t * 32 + i], s = fsin[t * 32 + i];
    float* q = g_q + (size_t)tq * NQ + h * HD;
    float x1 = q[i], x2 = q[i + 32];
    q[i]      = x1 * c - x2 * s;
    q[i + 32] = x1 * s + x2 * c;
}

// ------------------- bf16x3 split of q (post-rope) -------------------
__global__ void q_split()
{
    int i = blockIdx.x * blockDim.x + threadIdx.x;
    if (i >= TQ * NQ) return;
    float v = g_q[i];
    __nv_bfloat16 b0 = __float2bfloat16(v);
    float r1 = v - __bfloat162float(b0);
    __nv_bfloat16 b1 = __float2bfloat16(r1);
    float r2 = r1 - __bfloat162float(b1);
    g_qs0[i] = b0; g_qs1[i] = b1; g_qs2[i] = __float2bfloat16(r2);
}

// ------------------- weights for active rows -------------------
__global__ __launch_bounds__(256) void w_gemv(const float* __restrict__ x, const float* __restrict__ wproj)
{
    const int tq = blockIdx.x;
    const int tid = threadIdx.x;
    const int h = tid & 63;
    const int kg = tid >> 6;
    const float* xr = x + (size_t)(TB + tq) * HID + (size_t)kg * (HID / 4);
    const float* wp = wproj + (size_t)kg * (HID / 4) * NH + h;
    float acc = 0.0f;
    for (int k = 0; k < HID / 4; k += 4) {
        float4 xv = *(const float4*)(xr + k);
        acc = fmaf(xv.x, wp[(k + 0) * NH], acc);
        acc = fmaf(xv.y, wp[(k + 1) * NH], acc);
        acc = fmaf(xv.z, wp[(k + 2) * NH], acc);
        acc = fmaf(xv.w, wp[(k + 3) * NH], acc);
    }
    __shared__ float red[4][64];
    red[kg][h] = acc; __syncthreads();
    if (tid < 64) {
        float s = red[0][tid] + red[1][tid] + red[2][tid] + red[3][tid];
        s = (s * 0.125f) * 0.08838834764831843f;
        g_w[tq * NH + tid] = s;
    }
}

// ------------------- fixed fill for rows t < 2048 -------------------
__global__ void fill_fixed(float* __restrict__ out)
{
    size_t i = (size_t)blockIdx.x * blockDim.x + threadIdx.x;
    const size_t total = (size_t)TB * T_SEQ / 4;
    if (i >= total) return;
    size_t s4 = (i % (T_SEQ / 4)) * 4;
    float v = (s4 < TB) ? 0.0f : NEGBIG;
    ((float4*)out)[i] = make_float4(v, v, v, v);
}

// ------------------- exact top-2048 via radix select -------------------
__global__ __launch_bounds__(256) void topk_select(float* __restrict__ out)
{
    __shared__ unsigned keys[T_SEQ];
    __shared__ unsigned char flags[T_SEQ];
    __shared__ int redc[9];
    __shared__ int rlt[8], req[8];
    __shared__ int cnts[256];

    const int tq = blockIdx.x;
    const int t = TB + tq;
    const int n = t + 1;
    const int tid = threadIdx.x;
    const int lane = tid & 31, wid = tid >> 5;
    const float* srow = g_score + (size_t)tq * T_SEQ;

    for (int i = tid; i < n; i += 256) {
        unsigned b = __float_as_uint(srow[i]);
        keys[i] = b ^ ((b & 0x80000000u) ? 0xFFFFFFFFu : 0x80000000u);
    }
    __syncthreads();

    const int m0 = tq + 1;
    int m = m0;
    unsigned prefix = 0;
    for (int bit = 31; bit >= 0; bit--) {
        const unsigned pshift = prefix >> bit;
        int c = 0;
        for (int i = tid; i < n; i += 256)
            c += ((keys[i] >> bit) == pshift);
#pragma unroll
        for (int o = 16; o; o >>= 1) c += __shfl_xor_sync(0xffffffffu, c, o);
        if (lane == 0) redc[wid] = c;
        __syncthreads();
        if (tid == 0) {
            int tot = 0;
            for (int w = 0; w < 8; w++) tot += redc[w];
            redc[8] = tot;
        }
        __syncthreads();
        const int cnt = redc[8];
        if (m > cnt) { m -= cnt; prefix |= (1u << bit); }
        __syncthreads();
    }
    const unsigned theta = prefix;

    int clt = 0, ceq = 0;
    for (int i = tid; i < n; i += 256) {
        unsigned k = keys[i];
        clt += (k < theta);
        ceq += (k == theta);
    }
#pragma unroll
    for (int o = 16; o; o >>= 1) {
        clt += __shfl_xor_sync(0xffffffffu, clt, o);
        ceq += __shfl_xor_sync(0xffffffffu, ceq, o);
    }
    if (lane == 0) { rlt[wid] = clt; req[wid] = ceq; }
    __syncthreads();
    int count_lt = 0, count_eq = 0;
    for (int w = 0; w < 8; w++) { count_lt += rlt[w]; count_eq += req[w]; }
    const int keep_eq = count_eq - (m0 - count_lt);

    const int chunk = (n + 255) / 256;
    const int beg = tid * chunk;
    const int end = (beg + chunk < n) ? (beg + chunk) : n;
    int local = 0;
    for (int i = beg; i < end; i++) local += (keys[i] == theta);
    cnts[tid] = local;
    __syncthreads();
    if (tid == 0) {
        int run = 0;
        for (int i = 0; i < 256; i++) { int c = cnts[i]; cnts[i] = run; run += c; }
    }
    __syncthreads();
    int rank = cnts[tid];
    for (int i = beg; i < end; i++)
        if (keys[i] == theta) { flags[i] = (rank < keep_eq) ? 1 : 0; rank++; }
    __syncthreads();

    float* orow = out + (size_t)t * T_SEQ;
    for (int s = tid; s < T_SEQ; s += 256) {
        float v = NEGBIG;
        if (s < n) {
            unsigned k = keys[s];
            if (k > theta || (k == theta && flags[s])) v = 0.0f;
        }
        orow[s] = v;
    }
}

// ------------------- launch -------------------
extern "C" void kernel_launch(void* const* d_in, const int* in_sizes, int n_in,
                              void* d_out, int out_size)
{
    (void)in_sizes; (void)n_in; (void)out_size;
    const float* x     = (const float*)d_in[0];
    const float* qr    = (const float*)d_in[1];
    const float* fcos  = (const float*)d_in[2];
    const float* fsin  = (const float*)d_in[3];
    const float* wq_b  = (const float*)d_in[5];
    const float* wk_w  = (const float*)d_in[6];
    const float* kgam  = (const float*)d_in[7];
    const float* kbet  = (const float*)d_in[8];
    const float* wproj = (const float*)d_in[9];
    float* out = (float*)d_out;

    sgemm128<<<dim3(20, 1, KSPLIT), 256>>>(x, HID, wk_w, HD, 0, HD, KCHUNK, (size_t)T_SEQ * HD);
    k_postproc<<<T_SEQ, 128>>>(kgam, kbet, fcos, fsin);
    w_gemv<<<TQ, 256>>>(x, wproj);
    sgemm128<<<dim3(TQ / 128, NQ / 128, 1), 256>>>(qr + (size_t)TB * QLRD, QLRD, wq_b, NQ, 1, NQ, QLRD, 0);
    q_rope<<<(TQ * NH * 32 + 255) / 256, 256>>>(fcos, fsin);
    q_split<<<(TQ * NQ + 255) / 256, 256>>>();
    score_mma<<<dim3(T_SEQ / 128, 256), 256>>>();
    fill_fixed<<<((TB * T_SEQ / 4) + 255) / 256, 256>>>(out);
    topk_select<<<TQ, 256>>>(out);
}

// round 7
// speedup vs baseline: 1.1186x; 1.1062x over previous
#include <cuda_runtime.h>
#include <cuda_bf16.h>
#include <stdint.h>

#define T_SEQ 2560
#define HID   7168
#define QLRD  1536
#define NH    64
#define HD    128
#define NQ    8192
#define TQ    512
#define TB    2048
#define KSPLIT 8
#define KCHUNK (HID / KSPLIT)
#define NEGBIG (-1000000000.0f)

// ------------------- device scratch -------------------
__device__ __align__(16) float g_kpart[KSPLIT * T_SEQ * HD];
__device__ __align__(16) float g_q[TQ * NQ];
__device__ __align__(16) float g_w[TQ * NH];
__device__ __align__(16) float g_score[TQ * T_SEQ];
// bf16 3-way splits of q (post-rope) and k (post-LN/rope)
__device__ __align__(16) __nv_bfloat16 g_qs0[TQ * NQ];
__device__ __align__(16) __nv_bfloat16 g_qs1[TQ * NQ];
__device__ __align__(16) __nv_bfloat16 g_qs2[TQ * NQ];
__device__ __align__(16) __nv_bfloat16 g_ks0[T_SEQ * HD];
__device__ __align__(16) __nv_bfloat16 g_ks1[T_SEQ * HD];
__device__ __align__(16) __nv_bfloat16 g_ks2[T_SEQ * HD];

// ------------------- mma.sync / cp.async helpers (baseline PTX) -------------------
__device__ __forceinline__ void ldsm4(uint32_t* r, uint32_t addr) {
    asm volatile("ldmatrix.sync.aligned.m8n8.x4.shared.b16 {%0,%1,%2,%3},[%4];"
        : "=r"(r[0]), "=r"(r[1]), "=r"(r[2]), "=r"(r[3]) : "r"(addr));
}
__device__ __forceinline__ void mma16816(float* d, const uint32_t* a, const uint32_t* b) {
    asm volatile("mma.sync.aligned.m16n8k16.row.col.f32.bf16.bf16.f32 "
        "{%0,%1,%2,%3},{%4,%5,%6,%7},{%8,%9},{%0,%1,%2,%3};"
        : "+f"(d[0]), "+f"(d[1]), "+f"(d[2]), "+f"(d[3])
        : "r"(a[0]), "r"(a[1]), "r"(a[2]), "r"(a[3]), "r"(b[0]), "r"(b[1]));
}
__device__ __forceinline__ void cpa16(uint32_t dst, const void* src) {
    asm volatile("cp.async.cg.shared.global [%0],[%1],16;" :: "r"(dst), "l"(src));
}
#define CP_COMMIT() asm volatile("cp.async.commit_group;" ::: "memory")
#define CP_WAIT0()  asm volatile("cp.async.wait_group 0;" ::: "memory")

// ------------------- score: pipelined HMMA bf16 3-split/6-product + fused epilogue -----
// grid (20 s-tiles, 256 t-pair tiles), 256 threads. K stages: 6 products x 4 chunks of 32
#define LDT 40                      // padded row stride (bf16) for 32-col tiles
#define TILE_B (128 * LDT * 2)      // 10240 bytes per tile
__constant__ int c_aidx[6] = {0, 0, 1, 1, 0, 2};
__constant__ int c_bidx[6] = {0, 1, 0, 1, 2, 0};

__global__ __launch_bounds__(256, 2) void score_mma()
{
    __shared__ __nv_bfloat16 sT[2][2][128 * LDT];   // [buf][A=0/B=1]
    __shared__ float part[8][64];

    const int bs = blockIdx.x, bt = blockIdx.y;
    // causal skip: rows of this block are t in {TB+2bt, TB+2bt+1}; s >= bs*128 never kept if s > t_max
    if (bs * 128 > TB + 2 * bt + 1) return;

    const int tid = threadIdx.x, l = tid & 31, wid = tid >> 5;
    const int wm = wid & 3, wn = wid >> 2;

    const __nv_bfloat16* qa[3] = {g_qs0, g_qs1, g_qs2};
    const __nv_bfloat16* kb[3] = {g_ks0, g_ks1, g_ks2};

    float acc[2][8][4] = {};

    const uint32_t sbase = (uint32_t)__cvta_generic_to_shared(&sT[0][0][0]);
    // per-thread cp.async chunk coords: 512 16B chunks per tile, 2 per thread
    const int r0 = (tid + 0) >> 2,   g0 = (tid + 0) & 3;
    const int r1 = (tid + 256) >> 2, g1 = (tid + 256) & 3;

    // ldsm byte offsets within a tile
    uint32_t aOff[2], bOff[4];
#pragma unroll
    for (int mi = 0; mi < 2; mi++)
        aOff[mi] = ((wm * 32 + mi * 16 + (l & 15)) * LDT + (l >> 4) * 8) * 2;
#pragma unroll
    for (int nj = 0; nj < 4; nj++)
        bOff[nj] = ((wn * 64 + nj * 16 + ((l >> 4) * 8) + (l & 7)) * LDT + ((l >> 3) & 1) * 8) * 2;

    auto issue_stage = [&](int s, int buf) {
        const int p = s >> 2, kc = s & 3;
        const __nv_bfloat16* asrc = qa[c_aidx[p]] + (size_t)bt * 128 * HD + kc * 32;
        const __nv_bfloat16* bsrc = kb[c_bidx[p]] + (size_t)bs * 128 * HD + kc * 32;
        const uint32_t ab = sbase + buf * 2 * TILE_B;
        const uint32_t bb = ab + TILE_B;
        cpa16(ab + (r0 * LDT + g0 * 8) * 2, asrc + (size_t)r0 * HD + g0 * 8);
        cpa16(ab + (r1 * LDT + g1 * 8) * 2, asrc + (size_t)r1 * HD + g1 * 8);
        cpa16(bb + (r0 * LDT + g0 * 8) * 2, bsrc + (size_t)r0 * HD + g0 * 8);
        cpa16(bb + (r1 * LDT + g1 * 8) * 2, bsrc + (size_t)r1 * HD + g1 * 8);
        CP_COMMIT();
    };

    issue_stage(0, 0);
#pragma unroll 1
    for (int s = 0; s < 24; s++) {
        const int buf = s & 1;
        CP_WAIT0();
        __syncthreads();
        if (s + 1 < 24) issue_stage(s + 1, buf ^ 1);
        const uint32_t ab = sbase + buf * 2 * TILE_B;
        const uint32_t bb = ab + TILE_B;
#pragma unroll
        for (int ks = 0; ks < 2; ks++) {
            uint32_t af[2][4], bf[4][4];
            ldsm4(af[0], ab + aOff[0] + ks * 32);
            ldsm4(af[1], ab + aOff[1] + ks * 32);
#pragma unroll
            for (int nj = 0; nj < 4; nj++) ldsm4(bf[nj], bb + bOff[nj] + ks * 32);
#pragma unroll
            for (int mi = 0; mi < 2; mi++)
#pragma unroll
                for (int ni = 0; ni < 8; ni++)
                    mma16816(acc[mi][ni], af[mi], &bf[ni >> 1][(ni & 1) * 2]);
        }
    }

    // epilogue: relu * w, reduce over this warp's 32 head-rows, then cross-warp
    const int rbase = wm * 32 + (l >> 2);
    const float w0 = g_w[bt * 128 + rbase];
    const float w1 = g_w[bt * 128 + rbase + 8];
    const float w2 = g_w[bt * 128 + rbase + 16];
    const float w3 = g_w[bt * 128 + rbase + 24];
#pragma unroll
    for (int ni = 0; ni < 8; ni++) {
        float s0 = fmaxf(acc[0][ni][0], 0.0f) * w0 + fmaxf(acc[0][ni][2], 0.0f) * w1
                 + fmaxf(acc[1][ni][0], 0.0f) * w2 + fmaxf(acc[1][ni][2], 0.0f) * w3;
        float s1 = fmaxf(acc[0][ni][1], 0.0f) * w0 + fmaxf(acc[0][ni][3], 0.0f) * w1
                 + fmaxf(acc[1][ni][1], 0.0f) * w2 + fmaxf(acc[1][ni][3], 0.0f) * w3;
#pragma unroll
        for (int o = 4; o < 32; o <<= 1) {
            s0 += __shfl_xor_sync(0xffffffffu, s0, o);
            s1 += __shfl_xor_sync(0xffffffffu, s1, o);
        }
        if (l < 4) {
            part[wid][ni * 8 + 2 * l] = s0;
            part[wid][ni * 8 + 2 * l + 1] = s1;
        }
    }
    __syncthreads();
    {
        const int col = tid & 127, tt = tid >> 7;
        const int wa = (col >> 6) * 4 + tt * 2;
        float s = part[wa][col & 63] + part[wa + 1][col & 63];
        g_score[(size_t)(bt * 2 + tt) * T_SEQ + bs * 128 + col] = s;
    }
}

// ------------------- generic fp32 SGEMM 128x128 (exact path for k and q) ----------
__global__ __launch_bounds__(256) void sgemm128(
    const float* __restrict__ A, int lda,
    const float* __restrict__ B, int ldb,
    int which, int ldc, int kchunk, size_t zstride)
{
    __shared__ float As[8][132];
    __shared__ float Bs[8][132];

    const int tid = threadIdx.x;
    const int tx = tid & 15, ty = tid >> 4;
    const float* Ab = A + (size_t)blockIdx.x * 128 * lda;
    const float* Bb = B + (size_t)blockIdx.y * 128;
    float* Cb = (which == 0 ? g_kpart : g_q)
              + (size_t)blockIdx.z * zstride
              + (size_t)blockIdx.x * 128 * ldc + (size_t)blockIdx.y * 128;

    const int arow = tid >> 1, aoff = (tid & 1) * 4;
    const int bkk = tid >> 5, bcol = (tid & 31) * 4;

    float acc[8][8];
#pragma unroll
    for (int i = 0; i < 8; i++)
#pragma unroll
        for (int j = 0; j < 8; j++) acc[i][j] = 0.0f;

    int k0 = blockIdx.z * kchunk;
    const int kend = k0 + kchunk;
    for (; k0 < kend; k0 += 8) {
        float4 av = *(const float4*)(Ab + (size_t)arow * lda + k0 + aoff);
        float4 bv = *(const float4*)(Bb + (size_t)(k0 + bkk) * ldb + bcol);
        As[aoff + 0][arow] = av.x; As[aoff + 1][arow] = av.y;
        As[aoff + 2][arow] = av.z; As[aoff + 3][arow] = av.w;
        *(float4*)&Bs[bkk][bcol] = bv;
        __syncthreads();
#pragma unroll
        for (int kk = 0; kk < 8; kk++) {
            float4 a0 = *(const float4*)&As[kk][ty * 8];
            float4 a1 = *(const float4*)&As[kk][ty * 8 + 4];
            float4 b0 = *(const float4*)&Bs[kk][tx * 8];
            float4 b1 = *(const float4*)&Bs[kk][tx * 8 + 4];
            float a[8] = {a0.x, a0.y, a0.z, a0.w, a1.x, a1.y, a1.z, a1.w};
            float b[8] = {b0.x, b0.y, b0.z, b0.w, b1.x, b1.y, b1.z, b1.w};
#pragma unroll
            for (int i = 0; i < 8; i++)
#pragma unroll
                for (int j = 0; j < 8; j++)
                    acc[i][j] = fmaf(a[i], b[j], acc[i][j]);
        }
        __syncthreads();
    }
#pragma unroll
    for (int i = 0; i < 8; i++) {
        float* cr = Cb + (size_t)(ty * 8 + i) * ldc + tx * 8;
        *(float4*)cr       = make_float4(acc[i][0], acc[i][1], acc[i][2], acc[i][3]);
        *(float4*)(cr + 4) = make_float4(acc[i][4], acc[i][5], acc[i][6], acc[i][7]);
    }
}

// ------------------- split-K reduce + LayerNorm + RoPE + bf16x3 split for k -------------
__global__ __launch_bounds__(128) void k_postproc(
    const float* __restrict__ gamma, const float* __restrict__ beta,
    const float* __restrict__ fcos, const float* __restrict__ fsin)
{
    const int t = blockIdx.x;
    const int d = threadIdx.x;
    float v = 0.0f;
#pragma unroll
    for (int p = 0; p < KSPLIT; p++)
        v += g_kpart[(size_t)p * T_SEQ * HD + (size_t)t * HD + d];

    __shared__ float red[128];
    __shared__ float buf[128];
    red[d] = v; __syncthreads();
#pragma unroll
    for (int s = 64; s > 0; s >>= 1) { if (d < s) red[d] += red[d + s]; __syncthreads(); }
    const float mu = red[0] * (1.0f / 128.0f);
    __syncthreads();
    const float diff = v - mu;
    red[d] = diff * diff; __syncthreads();
#pragma unroll
    for (int s = 64; s > 0; s >>= 1) { if (d < s) red[d] += red[d + s]; __syncthreads(); }
    const float var = red[0] * (1.0f / 128.0f);
    const float inv = __frsqrt_rn(var + 1e-6f);
    const float nrm = diff * inv * gamma[d] + beta[d];
    buf[d] = nrm; __syncthreads();

    float outv;
    if (d < 32) {
        float c = fcos[t * 32 + d], s = fsin[t * 32 + d];
        outv = buf[d] * c - buf[d + 32] * s;
    } else if (d < 64) {
        float c = fcos[t * 32 + d - 32], s = fsin[t * 32 + d - 32];
        outv = buf[d - 32] * s + buf[d] * c;
    } else {
        outv = nrm;
    }
    __nv_bfloat16 b0 = __float2bfloat16(outv);
    float r1 = outv - __bfloat162float(b0);
    __nv_bfloat16 b1 = __float2bfloat16(r1);
    float r2 = r1 - __bfloat162float(b1);
    const size_t o = (size_t)t * HD + d;
    g_ks0[o] = b0; g_ks1[o] = b1; g_ks2[o] = __float2bfloat16(r2);
}

// ------------------- RoPE on q (fp32, in place) -------------------
__global__ void q_rope(const float* __restrict__ fcos, const float* __restrict__ fsin)
{
    int idx = blockIdx.x * blockDim.x + threadIdx.x;
    if (idx >= TQ * NH * 32) return;
    int i = idx & 31;
    int h = (idx >> 5) & 63;
    int tq = idx >> 11;
    int t = TB + tq;
    float c = fcos[t * 32 + i], s = fsin[t * 32 + i];
    float* q = g_q + (size_t)tq * NQ + h * HD;
    float x1 = q[i], x2 = q[i + 32];
    q[i]      = x1 * c - x2 * s;
    q[i + 32] = x1 * s + x2 * c;
}

// ------------------- bf16x3 split of q (post-rope) -------------------
__global__ void q_split()
{
    int i = blockIdx.x * blockDim.x + threadIdx.x;
    if (i >= TQ * NQ) return;
    float v = g_q[i];
    __nv_bfloat16 b0 = __float2bfloat16(v);
    float r1 = v - __bfloat162float(b0);
    __nv_bfloat16 b1 = __float2bfloat16(r1);
    float r2 = r1 - __bfloat162float(b1);
    g_qs0[i] = b0; g_qs1[i] = b1; g_qs2[i] = __float2bfloat16(r2);
}

// ------------------- weights for active rows -------------------
__global__ __launch_bounds__(256) void w_gemv(const float* __restrict__ x, const float* __restrict__ wproj)
{
    const int tq = blockIdx.x;
    const int tid = threadIdx.x;
    const int h = tid & 63;
    const int kg = tid >> 6;
    const float* xr = x + (size_t)(TB + tq) * HID + (size_t)kg * (HID / 4);
    const float* wp = wproj + (size_t)kg * (HID / 4) * NH + h;
    float acc = 0.0f;
    for (int k = 0; k < HID / 4; k += 4) {
        float4 xv = *(const float4*)(xr + k);
        acc = fmaf(xv.x, wp[(k + 0) * NH], acc);
        acc = fmaf(xv.y, wp[(k + 1) * NH], acc);
        acc = fmaf(xv.z, wp[(k + 2) * NH], acc);
        acc = fmaf(xv.w, wp[(k + 3) * NH], acc);
    }
    __shared__ float red[4][64];
    red[kg][h] = acc; __syncthreads();
    if (tid < 64) {
        float s = red[0][tid] + red[1][tid] + red[2][tid] + red[3][tid];
        s = (s * 0.125f) * 0.08838834764831843f;
        g_w[tq * NH + tid] = s;
    }
}

// ------------------- fixed fill for rows t < 2048 -------------------
__global__ void fill_fixed(float* __restrict__ out)
{
    size_t i = (size_t)blockIdx.x * blockDim.x + threadIdx.x;
    const size_t total = (size_t)TB * T_SEQ / 4;
    if (i >= total) return;
    size_t s4 = (i % (T_SEQ / 4)) * 4;
    float v = (s4 < TB) ? 0.0f : NEGBIG;
    ((float4*)out)[i] = make_float4(v, v, v, v);
}

// ------------------- exact top-2048 via radix select -------------------
__global__ __launch_bounds__(256) void topk_select(float* __restrict__ out)
{
    __shared__ unsigned keys[T_SEQ];
    __shared__ unsigned char flags[T_SEQ];
    __shared__ int redc[9];
    __shared__ int rlt[8], req[8];
    __shared__ int cnts[256];

    const int tq = blockIdx.x;
    const int t = TB + tq;
    const int n = t + 1;
    const int tid = threadIdx.x;
    const int lane = tid & 31, wid = tid >> 5;
    const float* srow = g_score + (size_t)tq * T_SEQ;

    for (int i = tid; i < n; i += 256) {
        unsigned b = __float_as_uint(srow[i]);
        keys[i] = b ^ ((b & 0x80000000u) ? 0xFFFFFFFFu : 0x80000000u);
    }
    __syncthreads();

    const int m0 = tq + 1;
    int m = m0;
    unsigned prefix = 0;
    for (int bit = 31; bit >= 0; bit--) {
        const unsigned pshift = prefix >> bit;
        int c = 0;
        for (int i = tid; i < n; i += 256)
            c += ((keys[i] >> bit) == pshift);
#pragma unroll
        for (int o = 16; o; o >>= 1) c += __shfl_xor_sync(0xffffffffu, c, o);
        if (lane == 0) redc[wid] = c;
        __syncthreads();
        if (tid == 0) {
            int tot = 0;
            for (int w = 0; w < 8; w++) tot += redc[w];
            redc[8] = tot;
        }
        __syncthreads();
        const int cnt = redc[8];
        if (m > cnt) { m -= cnt; prefix |= (1u << bit); }
        __syncthreads();
    }
    const unsigned theta = prefix;

    int clt = 0, ceq = 0;
    for (int i = tid; i < n; i += 256) {
        unsigned k = keys[i];
        clt += (k < theta);
        ceq += (k == theta);
    }
#pragma unroll
    for (int o = 16; o; o >>= 1) {
        clt += __shfl_xor_sync(0xffffffffu, clt, o);
        ceq += __shfl_xor_sync(0xffffffffu, ceq, o);
    }
    if (lane == 0) { rlt[wid] = clt; req[wid] = ceq; }
    __syncthreads();
    int count_lt = 0, count_eq = 0;
    for (int w = 0; w < 8; w++) { count_lt += rlt[w]; count_eq += req[w]; }
    const int keep_eq = count_eq - (m0 - count_lt);

    const int chunk = (n + 255) / 256;
    const int beg = tid * chunk;
    const int end = (beg + chunk < n) ? (beg + chunk) : n;
    int local = 0;
    for (int i = beg; i < end; i++) local += (keys[i] == theta);
    cnts[tid] = local;
    __syncthreads();
    if (tid == 0) {
        int run = 0;
        for (int i = 0; i < 256; i++) { int c = cnts[i]; cnts[i] = run; run += c; }
    }
    __syncthreads();
    int rank = cnts[tid];
    for (int i = beg; i < end; i++)
        if (keys[i] == theta) { flags[i] = (rank < keep_eq) ? 1 : 0; rank++; }
    __syncthreads();

    float* orow = out + (size_t)t * T_SEQ;
    for (int s = tid; s < T_SEQ; s += 256) {
        float v = NEGBIG;
        if (s < n) {
            unsigned k = keys[s];
            if (k > theta || (k == theta && flags[s])) v = 0.0f;
        }
        orow[s] = v;
    }
}

// ------------------- launch -------------------
extern "C" void kernel_launch(void* const* d_in, const int* in_sizes, int n_in,
                              void* d_out, int out_size)
{
    (void)in_sizes; (void)n_in; (void)out_size;
    const float* x     = (const float*)d_in[0];
    const float* qr    = (const float*)d_in[1];
    const float* fcos  = (const float*)d_in[2];
    const float* fsin  = (const float*)d_in[3];
    const float* wq_b  = (const float*)d_in[5];
    const float* wk_w  = (const float*)d_in[6];
    const float* kgam  = (const float*)d_in[7];
    const float* kbet  = (const float*)d_in[8];
    const float* wproj = (const float*)d_in[9];
    float* out = (float*)d_out;

    sgemm128<<<dim3(20, 1, KSPLIT), 256>>>(x, HID, wk_w, HD, 0, HD, KCHUNK, (size_t)T_SEQ * HD);
    k_postproc<<<T_SEQ, 128>>>(kgam, kbet, fcos, fsin);
    w_gemv<<<TQ, 256>>>(x, wproj);
    sgemm128<<<dim3(TQ / 128, NQ / 128, 1), 256>>>(qr + (size_t)TB * QLRD, QLRD, wq_b, NQ, 1, NQ, QLRD, 0);
    q_rope<<<(TQ * NH * 32 + 255) / 256, 256>>>(fcos, fsin);
    q_split<<<(TQ * NQ + 255) / 256, 256>>>();
    score_mma<<<dim3(T_SEQ / 128, 256), 256>>>();
    fill_fixed<<<((TB * T_SEQ / 4) + 255) / 256, 256>>>(out);
    topk_select<<<TQ, 256>>>(out);
}